// round 2
// baseline (speedup 1.0000x reference)
#include <cuda_runtime.h>
#include <cuda_bf16.h>
#include <math.h>

// Problem constants
#define BB 1024
#define LL 200
#define DD 128
#define HH 4
#define FFD 512
#define NLAYER 2
#define DKH 32
#define TT (BB * LL)          // 204800 tokens
#define SPLITK 40
#define FC_K 25600            // L*D

typedef unsigned long long ull;

// ---------------------------------------------------------------------------
// Scratch (static device allocations; no cudaMalloc allowed)
// ---------------------------------------------------------------------------
__device__ float g_x[(size_t)TT * DD];
__device__ float g_h[(size_t)TT * DD];
__device__ float g_q[(size_t)TT * DD];
__device__ float g_k[(size_t)TT * DD];
__device__ float g_v[(size_t)TT * DD];
__device__ float g_at[(size_t)TT * DD];
__device__ float g_ffn[(size_t)TT * FFD];
__device__ float g_part[(size_t)SPLITK * BB * DD];

// ---------------------------------------------------------------------------
// Packed f32x2 helpers (sm_103a)
// ---------------------------------------------------------------------------
__device__ __forceinline__ void ffma2(ull& d, ull a, ull b) {
    asm("fma.rn.f32x2 %0, %1, %2, %0;" : "+l"(d) : "l"(a), "l"(b));
}
__device__ __forceinline__ ull dup2(float x) {
    unsigned u = __float_as_uint(x);
    ull r;
    asm("mov.b64 %0, {%1, %1};" : "=l"(r) : "r"(u));
    return r;
}
__device__ __forceinline__ float2 unpk(ull v) {
    unsigned lo, hi;
    asm("mov.b64 {%0, %1}, %2;" : "=r"(lo), "=r"(hi) : "l"(v));
    return make_float2(__uint_as_float(lo), __uint_as_float(hi));
}
__device__ __forceinline__ float gelu_exact(float x) {
    return 0.5f * x * (1.0f + erff(x * 0.70710678118654752f));
}

// ---------------------------------------------------------------------------
// Embedding: x[b,l,:] = token_emb[seq[b,l]] + pos_emb[l]
// ---------------------------------------------------------------------------
__global__ void embed_kernel(const int* __restrict__ seqs,
                             const float4* __restrict__ te,
                             const float4* __restrict__ pe,
                             float4* __restrict__ x) {
    int idx = blockIdx.x * 256 + threadIdx.x;    // over TT*32 float4s (exact)
    int t = idx >> 5;
    int c = idx & 31;
    int l = t % LL;
    int tok = seqs[t];
    float4 a = te[(size_t)tok * 32 + c];
    float4 p = pe[(size_t)l * 32 + c];
    x[idx] = make_float4(a.x + p.x, a.y + p.y, a.z + p.z, a.w + p.w);
}

// ---------------------------------------------------------------------------
// LayerNorm: warp per token (D=128 = 32 lanes x float4)
// Launch with TT/8 blocks of 256 threads (8 tokens per block).
// ---------------------------------------------------------------------------
__global__ void ln_kernel(const float4* __restrict__ x,
                          const float* __restrict__ w,
                          const float* __restrict__ b,
                          float4* __restrict__ o) {
    int gt = blockIdx.x * 256 + threadIdx.x;
    int warp = gt >> 5;
    int lane = gt & 31;
    float4 v = x[(size_t)warp * 32 + lane];
    float s  = v.x + v.y + v.z + v.w;
    float sq = v.x * v.x + v.y * v.y + v.z * v.z + v.w * v.w;
#pragma unroll
    for (int off = 16; off; off >>= 1) {
        s  += __shfl_xor_sync(0xffffffffu, s, off);
        sq += __shfl_xor_sync(0xffffffffu, sq, off);
    }
    float mu  = s * (1.0f / 128.0f);
    float var = sq * (1.0f / 128.0f) - mu * mu;
    float rs  = rsqrtf(var + 1e-5f);
    float4 wv = *(const float4*)&w[lane * 4];
    float4 bv = *(const float4*)&b[lane * 4];
    float4 r;
    r.x = (v.x - mu) * rs * wv.x + bv.x;
    r.y = (v.y - mu) * rs * wv.y + bv.y;
    r.z = (v.z - mu) * rs * wv.z + bv.z;
    r.w = (v.w - mu) * rs * wv.w + bv.w;
    o[(size_t)warp * 32 + lane] = r;
}

// ---------------------------------------------------------------------------
// SGEMM: C[M,N] = A[M,K-chunk] @ W + epilogue.  BM=BN=128, BK=16, 256 thr,
// 8x8 microtile as 32 packed f32x2 accumulators.
// epi: 0 = +bias; 1 = +bias,gelu; 2 = +bias,+res; 3 = split-K partial (no bias)
// All shapes here are exact multiples of tile dims; no bounds checks.
// ---------------------------------------------------------------------------
#define GBM 128
#define GBN 128
#define GBK 16

__global__ __launch_bounds__(256, 2)
void sgemm_kernel(const float* __restrict__ A, const float* __restrict__ W,
                  const float* __restrict__ bias, const float* __restrict__ res,
                  float* __restrict__ C,
                  int M, int N, int lda, int kChunk, int epi) {
    __shared__ float As[GBK][GBM + 4];
    __shared__ float Bs[GBK][GBN];

    const int tid = threadIdx.x;
    const int bm = blockIdx.y * GBM;
    const int bn = blockIdx.x * GBN;
    const int k0 = blockIdx.z * kChunk;

    const int arow = tid >> 2;           // 0..63
    const int acol = (tid & 3) << 2;     // 0,4,8,12
    const int brow = tid >> 5;           // 0..7
    const int bcol = (tid & 31) << 2;    // 0..124
    const int ty = tid >> 4;             // 0..15
    const int tx = tid & 15;             // 0..15

    const float* Ab = A + (size_t)bm * lda + k0;
    const float* Wb = W + (size_t)k0 * N + bn;

    float4 a0, a1, b0, b1;
    // prefetch tile 0
    a0 = *(const float4*)(Ab + (size_t)arow * lda + acol);
    a1 = *(const float4*)(Ab + (size_t)(arow + 64) * lda + acol);
    b0 = *(const float4*)(Wb + (size_t)brow * N + bcol);
    b1 = *(const float4*)(Wb + (size_t)(brow + 8) * N + bcol);

    ull acc[8][4];
#pragma unroll
    for (int i = 0; i < 8; i++)
#pragma unroll
        for (int j = 0; j < 4; j++) acc[i][j] = 0ull;

    for (int kt = 0; kt < kChunk; kt += GBK) {
        __syncthreads();
        As[acol + 0][arow] = a0.x; As[acol + 1][arow] = a0.y;
        As[acol + 2][arow] = a0.z; As[acol + 3][arow] = a0.w;
        As[acol + 0][arow + 64] = a1.x; As[acol + 1][arow + 64] = a1.y;
        As[acol + 2][arow + 64] = a1.z; As[acol + 3][arow + 64] = a1.w;
        *(float4*)&Bs[brow][bcol] = b0;
        *(float4*)&Bs[brow + 8][bcol] = b1;
        __syncthreads();

        if (kt + GBK < kChunk) {
            const float* Ak = Ab + kt + GBK;
            const float* Wk = Wb + (size_t)(kt + GBK) * N;
            a0 = *(const float4*)(Ak + (size_t)arow * lda + acol);
            a1 = *(const float4*)(Ak + (size_t)(arow + 64) * lda + acol);
            b0 = *(const float4*)(Wk + (size_t)brow * N + bcol);
            b1 = *(const float4*)(Wk + (size_t)(brow + 8) * N + bcol);
        }

#pragma unroll
        for (int k = 0; k < GBK; k++) {
            float4 af0 = *(const float4*)&As[k][ty * 8];
            float4 af1 = *(const float4*)&As[k][ty * 8 + 4];
            ulonglong2 bb0 = *(const ulonglong2*)&Bs[k][tx * 8];
            ulonglong2 bb1 = *(const ulonglong2*)&Bs[k][tx * 8 + 4];
            ull bf[4] = {bb0.x, bb0.y, bb1.x, bb1.y};
            float av[8] = {af0.x, af0.y, af0.z, af0.w, af1.x, af1.y, af1.z, af1.w};
#pragma unroll
            for (int i = 0; i < 8; i++) {
                ull a2 = dup2(av[i]);
                ffma2(acc[i][0], a2, bf[0]);
                ffma2(acc[i][1], a2, bf[1]);
                ffma2(acc[i][2], a2, bf[2]);
                ffma2(acc[i][3], a2, bf[3]);
            }
        }
    }

    if (epi == 3) {
        float* Cp = C + (size_t)blockIdx.z * M * N + (size_t)bm * N + bn;
#pragma unroll
        for (int i = 0; i < 8; i++) {
            int row = ty * 8 + i;
            float2 p0 = unpk(acc[i][0]), p1 = unpk(acc[i][1]);
            float2 p2 = unpk(acc[i][2]), p3 = unpk(acc[i][3]);
            *(float4*)&Cp[(size_t)row * N + tx * 8]     = make_float4(p0.x, p0.y, p1.x, p1.y);
            *(float4*)&Cp[(size_t)row * N + tx * 8 + 4] = make_float4(p2.x, p2.y, p3.x, p3.y);
        }
        return;
    }

    float4 bi0 = *(const float4*)&bias[bn + tx * 8];
    float4 bi1 = *(const float4*)&bias[bn + tx * 8 + 4];
    float* Cp = C + (size_t)bm * N + bn;
    const float* Rp = (epi == 2) ? res + (size_t)bm * N + bn : nullptr;

#pragma unroll
    for (int i = 0; i < 8; i++) {
        int row = ty * 8 + i;
        float2 p0 = unpk(acc[i][0]), p1 = unpk(acc[i][1]);
        float2 p2 = unpk(acc[i][2]), p3 = unpk(acc[i][3]);
        float o[8] = {p0.x + bi0.x, p0.y + bi0.y, p1.x + bi0.z, p1.y + bi0.w,
                      p2.x + bi1.x, p2.y + bi1.y, p3.x + bi1.z, p3.y + bi1.w};
        if (epi == 1) {
#pragma unroll
            for (int j = 0; j < 8; j++) o[j] = gelu_exact(o[j]);
        } else if (epi == 2) {
            float4 r0 = *(const float4*)&Rp[(size_t)row * N + tx * 8];
            float4 r1 = *(const float4*)&Rp[(size_t)row * N + tx * 8 + 4];
            o[0] += r0.x; o[1] += r0.y; o[2] += r0.z; o[3] += r0.w;
            o[4] += r1.x; o[5] += r1.y; o[6] += r1.z; o[7] += r1.w;
        }
        *(float4*)&Cp[(size_t)row * N + tx * 8]     = make_float4(o[0], o[1], o[2], o[3]);
        *(float4*)&Cp[(size_t)row * N + tx * 8 + 4] = make_float4(o[4], o[5], o[6], o[7]);
    }
}

// ---------------------------------------------------------------------------
// Attention: one CTA per (b,h). K,V tiles in smem (broadcast reads), one-pass
// softmax (scores tiny; no max subtraction needed -> identical to ref softmax).
// Key-padding mask handled by warp-uniform skip (exp(-1e9) == 0 in f32).
// ---------------------------------------------------------------------------
#define ATTN_SMEM (2 * LL * DKH * 4)

__global__ __launch_bounds__(256)
void attn_kernel(const float* __restrict__ q, const float* __restrict__ k,
                 const float* __restrict__ v, const int* __restrict__ seqs,
                 float* __restrict__ out) {
    extern __shared__ float sm[];
    __shared__ int msk[LL];
    float* ks = sm;
    float* vs = sm + LL * DKH;

    int bh = blockIdx.x;
    int b = bh >> 2;
    int h = bh & (HH - 1);
    int tid = threadIdx.x;
    size_t rowbase = (size_t)b * LL;
    int co = h * DKH;

    for (int i = tid; i < LL * (DKH / 4); i += 256) {
        int r = i >> 3;
        int c = (i & 7) << 2;
        *(float4*)&ks[r * DKH + c] = *(const float4*)&k[(rowbase + r) * DD + co + c];
        *(float4*)&vs[r * DKH + c] = *(const float4*)&v[(rowbase + r) * DD + co + c];
    }
    for (int i = tid; i < LL; i += 256) msk[i] = seqs[rowbase + i] > 0;
    __syncthreads();

    if (tid >= LL) return;

    const float scale = 0.17677669529663687f;  // 1/sqrt(32)
    ull q2[16];
    const ull* qp = (const ull*)(q + (rowbase + tid) * DD + co);
#pragma unroll
    for (int t = 0; t < 16; t++) q2[t] = qp[t];

    ull acc[16];
#pragma unroll
    for (int t = 0; t < 16; t++) acc[t] = 0ull;
    float ssum = 0.0f;

    for (int j = 0; j < LL; j++) {
        if (!msk[j]) continue;   // thread-uniform branch
        const ull* kj = (const ull*)&ks[j * DKH];
        ull d2a = 0ull, d2b = 0ull;
#pragma unroll
        for (int t = 0; t < 8; t++) {
            ffma2(d2a, q2[2 * t], kj[2 * t]);
            ffma2(d2b, q2[2 * t + 1], kj[2 * t + 1]);
        }
        float2 da = unpk(d2a);
        float2 db = unpk(d2b);
        float p = __expf((da.x + da.y + db.x + db.y) * scale);
        ssum += p;
        ull p2 = dup2(p);
        const ull* vj = (const ull*)&vs[j * DKH];
#pragma unroll
        for (int t = 0; t < 16; t++) ffma2(acc[t], p2, vj[t]);
    }

    float inv = 1.0f / ssum;
    float* op = out + (rowbase + tid) * DD + co;
#pragma unroll
    for (int t = 0; t < 16; t++) {
        float2 a = unpk(acc[t]);
        *(float2*)&op[2 * t] = make_float2(a.x * inv, a.y * inv);
    }
}

// ---------------------------------------------------------------------------
// Final FC split-K reduce (deterministic fixed-order sum)
// ---------------------------------------------------------------------------
__global__ void fc_reduce_kernel(const float* __restrict__ part,
                                 const float* __restrict__ bias,
                                 float* __restrict__ out) {
    int idx = blockIdx.x * 256 + threadIdx.x;   // 131072 exact
    float s = bias[idx & (DD - 1)];
#pragma unroll
    for (int z = 0; z < SPLITK; z++) s += part[(size_t)z * (BB * DD) + idx];
    out[idx] = s;
}

// ---------------------------------------------------------------------------
// Host orchestration (graph-capturable: kernel launches only)
// ---------------------------------------------------------------------------
extern "C" void kernel_launch(void* const* d_in, const int* in_sizes, int n_in,
                              void* d_out, int out_size) {
    const int*   seqs = (const int*)d_in[0];
    const float* tok  = (const float*)d_in[1];
    const float* pos  = (const float*)d_in[2];
    const float* Wq = (const float*)d_in[3];
    const float* bq = (const float*)d_in[4];
    const float* Wk = (const float*)d_in[5];
    const float* bk = (const float*)d_in[6];
    const float* Wv = (const float*)d_in[7];
    const float* bv = (const float*)d_in[8];
    const float* Wo = (const float*)d_in[9];
    const float* bo = (const float*)d_in[10];
    const float* ln1w = (const float*)d_in[11];
    const float* ln1b = (const float*)d_in[12];
    const float* ln2w = (const float*)d_in[13];
    const float* ln2b = (const float*)d_in[14];
    const float* W1 = (const float*)d_in[15];
    const float* b1 = (const float*)d_in[16];
    const float* W2 = (const float*)d_in[17];
    const float* b2 = (const float*)d_in[18];
    const float* fcW = (const float*)d_in[19];
    const float* fcb = (const float*)d_in[20];
    float* out = (float*)d_out;

    void *px, *ph, *pq, *pk, *pv, *pat, *pffn, *ppart;
    cudaGetSymbolAddress(&px, g_x);
    cudaGetSymbolAddress(&ph, g_h);
    cudaGetSymbolAddress(&pq, g_q);
    cudaGetSymbolAddress(&pk, g_k);
    cudaGetSymbolAddress(&pv, g_v);
    cudaGetSymbolAddress(&pat, g_at);
    cudaGetSymbolAddress(&pffn, g_ffn);
    cudaGetSymbolAddress(&ppart, g_part);
    float* x = (float*)px;  float* h = (float*)ph;
    float* q = (float*)pq;  float* k = (float*)pk;  float* v = (float*)pv;
    float* at = (float*)pat; float* ffn = (float*)pffn; float* part = (float*)ppart;

    cudaFuncSetAttribute(attn_kernel, cudaFuncAttributeMaxDynamicSharedMemorySize, ATTN_SMEM);

    const int eltBlocks = (TT * 32) / 256;        // 25600
    const int lnBlocks  = TT / 8;                 // 25600 (warp-per-token, 8/block)
    embed_kernel<<<eltBlocks, 256>>>(seqs, (const float4*)tok, (const float4*)pos, (float4*)x);

    dim3 g1(1, TT / GBM, 1);      // N=128 GEMMs
    dim3 g2(FFD / GBN, TT / GBM, 1);  // FFN1 (N=512)

    for (int i = 0; i < NLAYER; i++) {
        size_t odd = (size_t)i * DD * DD;
        size_t odv = (size_t)i * DD;
        ln_kernel<<<lnBlocks, 256>>>((const float4*)x, ln1w + odv, ln1b + odv, (float4*)h);
        sgemm_kernel<<<g1, 256>>>(h, Wq + odd, bq + odv, nullptr, q, TT, DD, DD, DD, 0);
        sgemm_kernel<<<g1, 256>>>(h, Wk + odd, bk + odv, nullptr, k, TT, DD, DD, DD, 0);
        sgemm_kernel<<<g1, 256>>>(h, Wv + odd, bv + odv, nullptr, v, TT, DD, DD, DD, 0);
        attn_kernel<<<BB * HH, 256, ATTN_SMEM>>>(q, k, v, seqs, at);
        sgemm_kernel<<<g1, 256>>>(at, Wo + odd, bo + odv, x, x, TT, DD, DD, DD, 2);
        ln_kernel<<<lnBlocks, 256>>>((const float4*)x, ln2w + odv, ln2b + odv, (float4*)h);
        sgemm_kernel<<<g2, 256>>>(h, W1 + (size_t)i * DD * FFD, b1 + (size_t)i * FFD,
                                  nullptr, ffn, TT, FFD, DD, DD, 1);
        sgemm_kernel<<<g1, 256>>>(ffn, W2 + (size_t)i * FFD * DD, b2 + odv, x, x,
                                  TT, DD, FFD, FFD, 2);
    }

    // Final FC: [1024, 25600] @ [25600, 128], split-K=40, deterministic reduce
    dim3 gfc(1, BB / GBM, SPLITK);
    sgemm_kernel<<<gfc, 256>>>(x, fcW, nullptr, nullptr, part,
                               BB, DD, FC_K, FC_K / SPLITK, 3);
    fc_reduce_kernel<<<(BB * DD) / 256, 256>>>(part, fcb, out);
}

// round 4
// speedup vs baseline: 1.5928x; 1.5928x over previous
#include <cuda_runtime.h>
#include <cuda_bf16.h>
#include <math.h>
#include <stdint.h>

// Problem constants
#define BB 1024
#define LL 200
#define DD 128
#define HH 4
#define FFD 512
#define NLAYER 2
#define DKH 32
#define TT (BB * LL)          // 204800 tokens
#define SPLITK 40
#define FC_K 25600            // L*D

typedef unsigned long long ull;
typedef unsigned int u32;

// ---------------------------------------------------------------------------
// Scratch (static device allocations; no cudaMalloc allowed)
// ---------------------------------------------------------------------------
__device__ float g_x[(size_t)TT * DD];
__device__ float g_h[(size_t)TT * DD];
__device__ float g_q[(size_t)TT * DD];
__device__ float g_k[(size_t)TT * DD];
__device__ float g_v[(size_t)TT * DD];
__device__ float g_at[(size_t)TT * DD];
__device__ float g_ffn[(size_t)TT * FFD];
__device__ float g_part[(size_t)SPLITK * BB * DD];

// Transposed/split weights: [N][K] bf16, hi and lo parts.
// Layout: per layer {Wq,Wk,Wv,Wo (16384 each), W1 (65536), W2 (65536)} then fcW.
#define WT_PER_LAYER 196608
#define WT_FC_OFF (2 * WT_PER_LAYER)
#define WT_TOTAL (WT_FC_OFF + FC_K * DD)
__device__ __align__(16) __nv_bfloat16 g_wt_hi[WT_TOTAL];
__device__ __align__(16) __nv_bfloat16 g_wt_lo[WT_TOTAL];

__device__ __forceinline__ float gelu_exact(float x) {
    return 0.5f * x * (1.0f + erff(x * 0.70710678118654752f));
}

// ---------------------------------------------------------------------------
// Weight transpose + bf16 hi/lo split: W[K][N] f32 -> out[N][K] bf16 x2
// ---------------------------------------------------------------------------
__global__ void wconv_kernel(const float* __restrict__ W,
                             __nv_bfloat16* __restrict__ oh,
                             __nv_bfloat16* __restrict__ ol,
                             int K, int N) {
    __shared__ float t[32][33];
    int n0 = blockIdx.x * 32, k0 = blockIdx.y * 32;
    int tx = threadIdx.x, ty = threadIdx.y;   // 32 x 8
#pragma unroll
    for (int i = 0; i < 32; i += 8)
        t[ty + i][tx] = W[(size_t)(k0 + ty + i) * N + n0 + tx];
    __syncthreads();
#pragma unroll
    for (int i = 0; i < 32; i += 8) {
        int n = ty + i, k = tx;
        float v = t[k][n];
        __nv_bfloat16 h = __float2bfloat16(v);
        float lo = v - __bfloat162float(h);
        oh[(size_t)(n0 + n) * K + k0 + k] = h;
        ol[(size_t)(n0 + n) * K + k0 + k] = __float2bfloat16(lo);
    }
}

// ---------------------------------------------------------------------------
// Embedding
// ---------------------------------------------------------------------------
__global__ void embed_kernel(const int* __restrict__ seqs,
                             const float4* __restrict__ te,
                             const float4* __restrict__ pe,
                             float4* __restrict__ x) {
    int idx = blockIdx.x * 256 + threadIdx.x;
    int t = idx >> 5;
    int c = idx & 31;
    int l = t % LL;
    int tok = seqs[t];
    float4 a = te[(size_t)tok * 32 + c];
    float4 p = pe[(size_t)l * 32 + c];
    x[idx] = make_float4(a.x + p.x, a.y + p.y, a.z + p.z, a.w + p.w);
}

// ---------------------------------------------------------------------------
// LayerNorm: warp per token. Launch with TT/8 blocks of 256 threads.
// ---------------------------------------------------------------------------
__global__ void ln_kernel(const float4* __restrict__ x,
                          const float* __restrict__ w,
                          const float* __restrict__ b,
                          float4* __restrict__ o) {
    int gt = blockIdx.x * 256 + threadIdx.x;
    int warp = gt >> 5;
    int lane = gt & 31;
    float4 v = x[(size_t)warp * 32 + lane];
    float s  = v.x + v.y + v.z + v.w;
    float sq = v.x * v.x + v.y * v.y + v.z * v.z + v.w * v.w;
#pragma unroll
    for (int off = 16; off; off >>= 1) {
        s  += __shfl_xor_sync(0xffffffffu, s, off);
        sq += __shfl_xor_sync(0xffffffffu, sq, off);
    }
    float mu  = s * (1.0f / 128.0f);
    float var = sq * (1.0f / 128.0f) - mu * mu;
    float rs  = rsqrtf(var + 1e-5f);
    float4 wv = *(const float4*)&w[lane * 4];
    float4 bv = *(const float4*)&b[lane * 4];
    float4 r;
    r.x = (v.x - mu) * rs * wv.x + bv.x;
    r.y = (v.y - mu) * rs * wv.y + bv.y;
    r.z = (v.z - mu) * rs * wv.z + bv.z;
    r.w = (v.w - mu) * rs * wv.w + bv.w;
    o[(size_t)warp * 32 + lane] = r;
}

// ---------------------------------------------------------------------------
// Tensor-core GEMM via mma.sync bf16x3.
// C[128,128 tile] = A[M,K] @ W[K,N] tile (+ epilogue), fp32 accumulate.
// A: f32 [M][K] (lda = K), converted to bf16 hi/lo on the fly.
// W: pre-transposed bf16 hi/lo [N][K] (row stride = lda).
// epi: 0=+bias 1=+bias,gelu 2=+bias,+res 3=split-K partial
// ---------------------------------------------------------------------------
#define BKC 64
#define APAD 8
#define AROW (BKC + APAD)     // 72 bf16 per smem row
#define SM_ELEMS (128 * AROW) // 9216

#define MMA_B16(d, a, b) \
    asm volatile("mma.sync.aligned.m16n8k16.row.col.f32.bf16.bf16.f32 " \
        "{%0,%1,%2,%3}, {%4,%5,%6,%7}, {%8,%9}, {%0,%1,%2,%3};" \
        : "+f"((d)[0]), "+f"((d)[1]), "+f"((d)[2]), "+f"((d)[3]) \
        : "r"((a)[0]), "r"((a)[1]), "r"((a)[2]), "r"((a)[3]), \
          "r"((b)[0]), "r"((b)[1]))

__global__ __launch_bounds__(256, 2)
void tcore_gemm(const float* __restrict__ A,
                const __nv_bfloat16* __restrict__ WtHi,
                const __nv_bfloat16* __restrict__ WtLo,
                const float* __restrict__ bias, const float* __restrict__ res,
                float* __restrict__ C,
                int M, int N, int lda, int kChunk, int epi) {
    extern __shared__ __nv_bfloat16 smb[];
    __nv_bfloat16* As_hi = smb;
    __nv_bfloat16* As_lo = smb + SM_ELEMS;
    __nv_bfloat16* Bs_hi = smb + 2 * SM_ELEMS;
    __nv_bfloat16* Bs_lo = smb + 3 * SM_ELEMS;
    __shared__ float s_bias[128];

    const int tid = threadIdx.x;
    const int wid = tid >> 5;
    const int lane = tid & 31;
    const int lr = lane >> 2;   // 0..7
    const int lc = lane & 3;    // 0..3

    const int bm = blockIdx.y * 128;
    const int bn = blockIdx.x * 128;
    const int k0g = blockIdx.z * kChunk;
    const int nchunks = kChunk / BKC;

    const int wm = (wid & 3) * 32;   // warp M offset
    const int wn = (wid >> 2) * 64;  // warp N offset

    if (epi != 3 && tid < 128) s_bias[tid] = bias[bn + tid];

    float acc[2][8][4];
#pragma unroll
    for (int i = 0; i < 2; i++)
#pragma unroll
        for (int j = 0; j < 8; j++)
#pragma unroll
            for (int t = 0; t < 4; t++) acc[i][j][t] = 0.0f;

    for (int kc = 0; kc < nchunks; kc++) {
        const int kbase = k0g + kc * BKC;

        // ---- A fill: 128 rows x 64 k, f32 -> bf16 hi/lo ----
        {
            const float* Ag = A + (size_t)bm * lda + kbase;
#pragma unroll
            for (int p = 0; p < 8; p++) {
                int idx = p * 256 + tid;
                int m = idx >> 4;
                int kq = idx & 15;
                float4 vv = *(const float4*)(Ag + (size_t)m * lda + kq * 4);
                u32 h01, h23, l01, l23;
                asm("cvt.rn.bf16x2.f32 %0, %1, %2;" : "=r"(h01) : "f"(vv.y), "f"(vv.x));
                asm("cvt.rn.bf16x2.f32 %0, %1, %2;" : "=r"(h23) : "f"(vv.w), "f"(vv.z));
                float r0 = vv.x - __uint_as_float(h01 << 16);
                float r1 = vv.y - __uint_as_float(h01 & 0xffff0000u);
                float r2 = vv.z - __uint_as_float(h23 << 16);
                float r3 = vv.w - __uint_as_float(h23 & 0xffff0000u);
                asm("cvt.rn.bf16x2.f32 %0, %1, %2;" : "=r"(l01) : "f"(r1), "f"(r0));
                asm("cvt.rn.bf16x2.f32 %0, %1, %2;" : "=r"(l23) : "f"(r3), "f"(r2));
                u32 o = (u32)m * AROW + kq * 4;
                *(u32*)&As_hi[o] = h01; *(u32*)&As_hi[o + 2] = h23;
                *(u32*)&As_lo[o] = l01; *(u32*)&As_lo[o + 2] = l23;
            }
        }
        // ---- B fill: 128 n x 64 k bf16 hi/lo, straight copies ----
        {
#pragma unroll
            for (int p = 0; p < 4; p++) {
                int idx = p * 256 + tid;
                int n = idx >> 3;
                int kq = idx & 7;
                size_t go = (size_t)(bn + n) * lda + kbase + kq * 8;
                uint4 vh = *(const uint4*)(WtHi + go);
                uint4 vl = *(const uint4*)(WtLo + go);
                u32 o = (u32)n * AROW + kq * 8;
                *(uint4*)&Bs_hi[o] = vh;
                *(uint4*)&Bs_lo[o] = vl;
            }
        }
        __syncthreads();

        // ---- compute: 4 k16 steps ----
#pragma unroll
        for (int ks = 0; ks < 4; ks++) {
            const int kk = ks * 16;
            u32 ah[2][4], al[2][4];
#pragma unroll
            for (int i = 0; i < 2; i++) {
                u32 ro = (u32)(wm + i * 16 + lr) * AROW + kk + lc * 2;
                ah[i][0] = *(const u32*)&As_hi[ro];
                ah[i][1] = *(const u32*)&As_hi[ro + 8 * AROW];
                ah[i][2] = *(const u32*)&As_hi[ro + 8];
                ah[i][3] = *(const u32*)&As_hi[ro + 8 * AROW + 8];
                al[i][0] = *(const u32*)&As_lo[ro];
                al[i][1] = *(const u32*)&As_lo[ro + 8 * AROW];
                al[i][2] = *(const u32*)&As_lo[ro + 8];
                al[i][3] = *(const u32*)&As_lo[ro + 8 * AROW + 8];
            }
#pragma unroll
            for (int j = 0; j < 8; j++) {
                u32 bo = (u32)(wn + j * 8 + lr) * AROW + kk + lc * 2;
                u32 bh[2], bl[2];
                bh[0] = *(const u32*)&Bs_hi[bo];
                bh[1] = *(const u32*)&Bs_hi[bo + 8];
                bl[0] = *(const u32*)&Bs_lo[bo];
                bl[1] = *(const u32*)&Bs_lo[bo + 8];
                MMA_B16(acc[0][j], ah[0], bh);
                MMA_B16(acc[1][j], ah[1], bh);
                MMA_B16(acc[0][j], ah[0], bl);
                MMA_B16(acc[1][j], ah[1], bl);
                MMA_B16(acc[0][j], al[0], bh);
                MMA_B16(acc[1][j], al[1], bh);
            }
        }
        __syncthreads();
    }

    // ---- epilogue ----
    if (epi == 3) {
        float* Cz = C + (size_t)blockIdx.z * M * N;
#pragma unroll
        for (int i = 0; i < 2; i++)
#pragma unroll
            for (int j = 0; j < 8; j++) {
                int r0 = bm + wm + i * 16 + lr;
                int cc = bn + wn + j * 8 + lc * 2;
                float* d = acc[i][j];
                *(float2*)&Cz[(size_t)r0 * N + cc]       = make_float2(d[0], d[1]);
                *(float2*)&Cz[(size_t)(r0 + 8) * N + cc] = make_float2(d[2], d[3]);
            }
        return;
    }

#pragma unroll
    for (int i = 0; i < 2; i++)
#pragma unroll
        for (int j = 0; j < 8; j++) {
            int r0 = bm + wm + i * 16 + lr;
            int cl = wn + j * 8 + lc * 2;     // col within 128 block
            int cc = bn + cl;
            float* d = acc[i][j];
            float b0 = s_bias[cl], b1 = s_bias[cl + 1];
            float v00 = d[0] + b0, v01 = d[1] + b1;
            float v10 = d[2] + b0, v11 = d[3] + b1;
            if (epi == 1) {
                v00 = gelu_exact(v00); v01 = gelu_exact(v01);
                v10 = gelu_exact(v10); v11 = gelu_exact(v11);
            } else if (epi == 2) {
                float2 q0 = *(const float2*)&res[(size_t)r0 * N + cc];
                float2 q1 = *(const float2*)&res[(size_t)(r0 + 8) * N + cc];
                v00 += q0.x; v01 += q0.y; v10 += q1.x; v11 += q1.y;
            }
            *(float2*)&C[(size_t)r0 * N + cc]       = make_float2(v00, v01);
            *(float2*)&C[(size_t)(r0 + 8) * N + cc] = make_float2(v10, v11);
        }
}

// ---------------------------------------------------------------------------
// Attention: one CTA per (b,h). K,V in smem, one-pass softmax.
// ---------------------------------------------------------------------------
#define ATTN_SMEM (2 * LL * DKH * 4)

__global__ __launch_bounds__(256)
void attn_kernel(const float* __restrict__ q, const float* __restrict__ k,
                 const float* __restrict__ v, const int* __restrict__ seqs,
                 float* __restrict__ out) {
    extern __shared__ float sm[];
    __shared__ int msk[LL];
    float* ks = sm;
    float* vs = sm + LL * DKH;

    int bh = blockIdx.x;
    int b = bh >> 2;
    int h = bh & (HH - 1);
    int tid = threadIdx.x;
    size_t rowbase = (size_t)b * LL;
    int co = h * DKH;

    for (int i = tid; i < LL * (DKH / 4); i += 256) {
        int r = i >> 3;
        int c = (i & 7) << 2;
        *(float4*)&ks[r * DKH + c] = *(const float4*)&k[(rowbase + r) * DD + co + c];
        *(float4*)&vs[r * DKH + c] = *(const float4*)&v[(rowbase + r) * DD + co + c];
    }
    for (int i = tid; i < LL; i += 256) msk[i] = seqs[rowbase + i] > 0;
    __syncthreads();

    if (tid >= LL) return;

    const float scale = 0.17677669529663687f;
    float qr[32];
    const float4* qp = (const float4*)(q + (rowbase + tid) * DD + co);
#pragma unroll
    for (int t = 0; t < 8; t++) {
        float4 vv = qp[t];
        qr[4 * t] = vv.x; qr[4 * t + 1] = vv.y; qr[4 * t + 2] = vv.z; qr[4 * t + 3] = vv.w;
    }

    float acc[32];
#pragma unroll
    for (int t = 0; t < 32; t++) acc[t] = 0.0f;
    float ssum = 0.0f;

    for (int j = 0; j < LL; j++) {
        if (!msk[j]) continue;
        const float* kj = &ks[j * DKH];
        float d = 0.0f;
#pragma unroll
        for (int t = 0; t < 32; t++) d += qr[t] * kj[t];
        float p = __expf(d * scale);
        ssum += p;
        const float* vj = &vs[j * DKH];
#pragma unroll
        for (int t = 0; t < 32; t++) acc[t] += p * vj[t];
    }

    float inv = 1.0f / ssum;
    float* op = out + (rowbase + tid) * DD + co;
#pragma unroll
    for (int t = 0; t < 8; t++)
        *(float4*)&op[4 * t] = make_float4(acc[4 * t] * inv, acc[4 * t + 1] * inv,
                                           acc[4 * t + 2] * inv, acc[4 * t + 3] * inv);
}

// ---------------------------------------------------------------------------
// Final FC split-K reduce (deterministic fixed-order sum)
// ---------------------------------------------------------------------------
__global__ void fc_reduce_kernel(const float* __restrict__ part,
                                 const float* __restrict__ bias,
                                 float* __restrict__ out) {
    int idx = blockIdx.x * 256 + threadIdx.x;
    float s = bias[idx & (DD - 1)];
#pragma unroll
    for (int z = 0; z < SPLITK; z++) s += part[(size_t)z * (BB * DD) + idx];
    out[idx] = s;
}

// ---------------------------------------------------------------------------
// Host orchestration (graph-capturable)
// ---------------------------------------------------------------------------
extern "C" void kernel_launch(void* const* d_in, const int* in_sizes, int n_in,
                              void* d_out, int out_size) {
    const int*   seqs = (const int*)d_in[0];
    const float* tok  = (const float*)d_in[1];
    const float* pos  = (const float*)d_in[2];
    const float* Wq = (const float*)d_in[3];
    const float* bq = (const float*)d_in[4];
    const float* Wk = (const float*)d_in[5];
    const float* bk = (const float*)d_in[6];
    const float* Wv = (const float*)d_in[7];
    const float* bv = (const float*)d_in[8];
    const float* Wo = (const float*)d_in[9];
    const float* bo = (const float*)d_in[10];
    const float* ln1w = (const float*)d_in[11];
    const float* ln1b = (const float*)d_in[12];
    const float* ln2w = (const float*)d_in[13];
    const float* ln2b = (const float*)d_in[14];
    const float* W1 = (const float*)d_in[15];
    const float* b1 = (const float*)d_in[16];
    const float* W2 = (const float*)d_in[17];
    const float* b2 = (const float*)d_in[18];
    const float* fcW = (const float*)d_in[19];
    const float* fcb = (const float*)d_in[20];
    float* out = (float*)d_out;

    void *px, *ph, *pq, *pk, *pv, *pat, *pffn, *ppart, *pwh, *pwl;
    cudaGetSymbolAddress(&px, g_x);
    cudaGetSymbolAddress(&ph, g_h);
    cudaGetSymbolAddress(&pq, g_q);
    cudaGetSymbolAddress(&pk, g_k);
    cudaGetSymbolAddress(&pv, g_v);
    cudaGetSymbolAddress(&pat, g_at);
    cudaGetSymbolAddress(&pffn, g_ffn);
    cudaGetSymbolAddress(&ppart, g_part);
    cudaGetSymbolAddress(&pwh, g_wt_hi);
    cudaGetSymbolAddress(&pwl, g_wt_lo);
    float* x = (float*)px;  float* h = (float*)ph;
    float* q = (float*)pq;  float* k = (float*)pk;  float* v = (float*)pv;
    float* at = (float*)pat; float* ffn = (float*)pffn; float* part = (float*)ppart;
    __nv_bfloat16* wh = (__nv_bfloat16*)pwh;
    __nv_bfloat16* wl = (__nv_bfloat16*)pwl;

    cudaFuncSetAttribute(attn_kernel, cudaFuncAttributeMaxDynamicSharedMemorySize, ATTN_SMEM);
    cudaFuncSetAttribute(tcore_gemm, cudaFuncAttributeMaxDynamicSharedMemorySize,
                         4 * SM_ELEMS * 2);
    const int GSM = 4 * SM_ELEMS * 2;   // 73728 bytes

    // ---- weight transpose/split (per matrix) ----
    dim3 wb(32, 8);
    for (int i = 0; i < NLAYER; i++) {
        size_t lw = (size_t)i * WT_PER_LAYER;
        wconv_kernel<<<dim3(4, 4), wb>>>(Wq + (size_t)i * DD * DD, wh + lw, wl + lw, DD, DD);
        wconv_kernel<<<dim3(4, 4), wb>>>(Wk + (size_t)i * DD * DD, wh + lw + 16384, wl + lw + 16384, DD, DD);
        wconv_kernel<<<dim3(4, 4), wb>>>(Wv + (size_t)i * DD * DD, wh + lw + 32768, wl + lw + 32768, DD, DD);
        wconv_kernel<<<dim3(4, 4), wb>>>(Wo + (size_t)i * DD * DD, wh + lw + 49152, wl + lw + 49152, DD, DD);
        wconv_kernel<<<dim3(16, 4), wb>>>(W1 + (size_t)i * DD * FFD, wh + lw + 65536, wl + lw + 65536, DD, FFD);
        wconv_kernel<<<dim3(4, 16), wb>>>(W2 + (size_t)i * FFD * DD, wh + lw + 131072, wl + lw + 131072, FFD, DD);
    }
    wconv_kernel<<<dim3(4, FC_K / 32), wb>>>(fcW, wh + WT_FC_OFF, wl + WT_FC_OFF, FC_K, DD);

    const int eltBlocks = (TT * 32) / 256;        // 25600
    const int lnBlocks  = TT / 8;                 // 25600
    embed_kernel<<<eltBlocks, 256>>>(seqs, (const float4*)tok, (const float4*)pos, (float4*)x);

    dim3 g1(1, TT / 128, 1);          // N=128 GEMMs
    dim3 g2(FFD / 128, TT / 128, 1);  // FFN1 (N=512)

    for (int i = 0; i < NLAYER; i++) {
        size_t lw = (size_t)i * WT_PER_LAYER;
        size_t odv = (size_t)i * DD;
        ln_kernel<<<lnBlocks, 256>>>((const float4*)x, ln1w + odv, ln1b + odv, (float4*)h);
        tcore_gemm<<<g1, 256, GSM>>>(h, wh + lw,         wl + lw,         bq + odv, nullptr, q, TT, DD, DD, DD, 0);
        tcore_gemm<<<g1, 256, GSM>>>(h, wh + lw + 16384, wl + lw + 16384, bk + odv, nullptr, k, TT, DD, DD, DD, 0);
        tcore_gemm<<<g1, 256, GSM>>>(h, wh + lw + 32768, wl + lw + 32768, bv + odv, nullptr, v, TT, DD, DD, DD, 0);
        attn_kernel<<<BB * HH, 256, ATTN_SMEM>>>(q, k, v, seqs, at);
        tcore_gemm<<<g1, 256, GSM>>>(at, wh + lw + 49152, wl + lw + 49152, bo + odv, x, x, TT, DD, DD, DD, 2);
        ln_kernel<<<lnBlocks, 256>>>((const float4*)x, ln2w + odv, ln2b + odv, (float4*)h);
        tcore_gemm<<<g2, 256, GSM>>>(h, wh + lw + 65536, wl + lw + 65536,
                                     b1 + (size_t)i * FFD, nullptr, ffn, TT, FFD, DD, DD, 1);
        tcore_gemm<<<g1, 256, GSM>>>(ffn, wh + lw + 131072, wl + lw + 131072,
                                     b2 + odv, x, x, TT, DD, FFD, FFD, 2);
    }

    // Final FC: [1024, 25600] @ [25600, 128], split-K=40 x kChunk=640
    dim3 gfc(1, BB / 128, SPLITK);
    tcore_gemm<<<gfc, 256, GSM>>>(x, wh + WT_FC_OFF, wl + WT_FC_OFF, nullptr, nullptr, part,
                                  BB, DD, FC_K, FC_K / SPLITK, 3);
    fc_reduce_kernel<<<(BB * DD) / 256, 256>>>(part, fcb, out);
}